// round 1
// baseline (speedup 1.0000x reference)
#include <cuda_runtime.h>
#include <cuda_bf16.h>
#include <cstdint>

// Problem constants (fixed shapes per reference)
#define B 32
#define N 1024
#define M 1024
#define INV_EPS 20.0f
#define TOL 0.001f
#define MAX_ITER 50

// ---------------------------------------------------------------------------
// Device scratch (static allocation — allowed; no cudaMalloc anywhere)
// ---------------------------------------------------------------------------
__device__ float g_K[(size_t)B * N * M];   // 128 MB: K = exp(-cost/eps)
__device__ float g_u[B * N];               // linear-domain u = exp(log_u)
__device__ float g_v[B * M];               // linear-domain v = exp(log_v)
__device__ float g_partial[B * 8 * M];     // col-pass partial sums (8 n-chunks)
__device__ int   g_changeBits;             // float bits of max |log(u_new/u_old)|
__device__ int   g_done;                   // convergence flag

// ---------------------------------------------------------------------------
// Init: reset all iteration state (must run every kernel_launch / replay)
// ---------------------------------------------------------------------------
__global__ void initKernel() {
    int i = blockIdx.x * blockDim.x + threadIdx.x;
    if (i < B * N) g_u[i] = 1.0f;          // exp(log_u0 = 0)
    if (i < B * M) g_v[i] = 1.0f;          // exp(log_v0 = 0)
    if (i == 0) { g_changeBits = 0; g_done = 0; }
}

// ---------------------------------------------------------------------------
// Precompute K = exp(-cost * (1/eps)). One float4 per thread, exact grid.
// ---------------------------------------------------------------------------
__global__ void __launch_bounds__(256) expKernel(const float* __restrict__ cost) {
    size_t i = ((size_t)blockIdx.x * 256 + threadIdx.x) * 4;
    float4 c = *(const float4*)(cost + i);
    float4 k;
    k.x = expf(-INV_EPS * c.x);
    k.y = expf(-INV_EPS * c.y);
    k.z = expf(-INV_EPS * c.z);
    k.w = expf(-INV_EPS * c.w);
    *(float4*)(g_K + i) = k;
}

// ---------------------------------------------------------------------------
// Row update: u[b,n] = (src[b,n]+1e-12) / sum_m K[b,n,m] * v[b,m]
// One warp per row, 8 rows (one batch slice) per 256-thread block.
// Also accumulates max |log(u_new/u_old)| for the convergence check.
// ---------------------------------------------------------------------------
__global__ void __launch_bounds__(256) rowKernel(const float* __restrict__ src) {
    if (g_done) return;
    __shared__ float sv[M];
    int blk = blockIdx.x;                 // 4096 blocks, 8 rows each
    int b = blk >> 7;                     // 128 blocks per batch
    int t = threadIdx.x;
    #pragma unroll
    for (int j = t; j < M; j += 256) sv[j] = g_v[(b << 10) + j];
    __syncthreads();

    int w = t >> 5, lane = t & 31;
    int row = (blk << 3) + w;             // global row in [0, B*N)
    const float4* Kr = (const float4*)(g_K + ((size_t)row << 10));
    float s = 0.0f;
    #pragma unroll
    for (int it = 0; it < 8; it++) {
        int idx = it * 32 + lane;         // float4 index 0..255
        float4 k  = Kr[idx];
        float4 vv = *(const float4*)(sv + 4 * idx);
        s += k.x * vv.x;
        s += k.y * vv.y;
        s += k.z * vv.z;
        s += k.w * vv.w;
    }
    #pragma unroll
    for (int o = 16; o; o >>= 1) s += __shfl_xor_sync(0xFFFFFFFFu, s, o);

    if (lane == 0) {
        float old = g_u[row];
        float r   = src[row] + 1e-12f;
        float nu  = r / s;
        g_u[row]  = nu;
        float ch  = fabsf(logf(nu / old));   // == |log_u_new - log_u_old|
        atomicMax(&g_changeBits, __float_as_int(ch)); // ch >= 0: bit-monotonic
    }
}

// ---------------------------------------------------------------------------
// Col update partials: partial[b,nc,m] = sum_{n in chunk nc} K[b,n,m]*u[b,n]
// grid = (4 col-tiles of 256, 8 n-chunks of 128, 32 batches) = 1024 blocks.
// Thread handles one column m; loads are fully coalesced (contiguous m).
// ---------------------------------------------------------------------------
__global__ void __launch_bounds__(256) colKernel() {
    if (g_done) return;
    __shared__ float su[128];
    int ct = blockIdx.x, nc = blockIdx.y, b = blockIdx.z;
    int t = threadIdx.x;
    if (t < 128) su[t] = g_u[(b << 10) + (nc << 7) + t];
    __syncthreads();

    int m = (ct << 8) + t;
    const float* p = g_K + ((size_t)b << 20) + ((size_t)(nc << 7) << 10) + m;
    float s0 = 0, s1 = 0, s2 = 0, s3 = 0;
    #pragma unroll
    for (int r = 0; r < 128; r += 4) {
        s0 += p[0]      * su[r + 0];
        s1 += p[1024]   * su[r + 1];
        s2 += p[2048]   * su[r + 2];
        s3 += p[3072]   * su[r + 3];
        p += 4096;
    }
    g_partial[(((b << 3) + nc) << 10) + m] = (s0 + s1) + (s2 + s3);
}

// ---------------------------------------------------------------------------
// Col finalize: v[b,m] = (tgt[b,m]+1e-12) / sum_{nc<8} partial[b,nc,m]
// ---------------------------------------------------------------------------
__global__ void __launch_bounds__(256) colFinKernel(const float* __restrict__ tgt) {
    if (g_done) return;
    int i = blockIdx.x * 256 + threadIdx.x;   // 0..B*M
    int b = i >> 10, m = i & 1023;
    float s = 0.0f;
    #pragma unroll
    for (int j = 0; j < 8; j++) s += g_partial[(((b << 3) + j) << 10) + m];
    g_v[i] = (tgt[i] + 1e-12f) / s;
}

// ---------------------------------------------------------------------------
// Convergence check: runs AFTER the col update (matches reference ordering —
// the converging iteration still completes its v update, then freezes).
// ---------------------------------------------------------------------------
__global__ void checkKernel() {
    float ch = __int_as_float(g_changeBits);
    g_changeBits = 0;
    if (ch < TOL) g_done = 1;
}

// ---------------------------------------------------------------------------
// Output: T[b,n,m] = u[b,n] * K[b,n,m] * v[b,m]  (== exp(log_u+log_K+log_v))
// ---------------------------------------------------------------------------
__global__ void __launch_bounds__(256) outKernel(float* __restrict__ out) {
    unsigned i4 = blockIdx.x * 256 + threadIdx.x;   // float4 index
    size_t e = (size_t)i4 << 2;
    unsigned row = (unsigned)(e >> 10);             // b*N + n
    unsigned b = row >> 10;
    float u = g_u[row];
    float4 vv = *(const float4*)(g_v + (b << 10) + (unsigned)(e & 1023));
    float4 k  = *(const float4*)(g_K + e);
    float4 o;
    o.x = u * k.x * vv.x;
    o.y = u * k.y * vv.y;
    o.z = u * k.z * vv.z;
    o.w = u * k.w * vv.w;
    *(float4*)(out + e) = o;
}

// ---------------------------------------------------------------------------
// Launch: graph-capturable, allocation-free, deterministic per replay.
// ---------------------------------------------------------------------------
extern "C" void kernel_launch(void* const* d_in, const int* in_sizes, int n_in,
                              void* d_out, int out_size) {
    const float* cost = (const float*)d_in[0];  // [B,N,M]
    const float* src  = (const float*)d_in[1];  // [B,N]
    const float* tgt  = (const float*)d_in[2];  // [B,M]
    float* out = (float*)d_out;                 // [B,N,M]

    initKernel<<<(B * N + 255) / 256, 256>>>();
    expKernel<<<(B * N * M) / (256 * 4), 256>>>(cost);   // 32768 blocks

    dim3 colGrid(4, 8, B);
    for (int it = 0; it < MAX_ITER; it++) {
        rowKernel<<<(B * N) / 8, 256>>>(src);            // 4096 blocks
        colKernel<<<colGrid, 256>>>();
        colFinKernel<<<(B * M) / 256, 256>>>(tgt);
        checkKernel<<<1, 1>>>();
    }

    outKernel<<<(B * N * M) / (256 * 4), 256>>>(out);    // 32768 blocks
}

// round 2
// speedup vs baseline: 2.1518x; 2.1518x over previous
#include <cuda_runtime.h>
#include <cstdint>

#define B 32
#define N 1024
#define M 1024
#define TOL 0.001f
#define MAX_ITER 50
#define GRID 128          // 4 blocks per batch; <= SM count => co-resident
#define TPB 512

// ---------------------------------------------------------------------------
// Device scratch (static: no allocation anywhere)
// ---------------------------------------------------------------------------
__device__ float    g_K[(size_t)B * N * M];      // 128 MB
__device__ float    g_u[B * N];
__device__ float    g_partial[2 * B * 4 * M];    // double-buffered col partials
__device__ int      g_change[MAX_ITER];          // per-iter max |dlog u| (float bits)
__device__ unsigned g_barCount;
__device__ unsigned g_barGen;

// ---------------------------------------------------------------------------
__global__ void initKernel() {
    int i = threadIdx.x;
    if (i < MAX_ITER) g_change[i] = 0;
    if (i == 0) { g_barCount = 0u; g_barGen = 0u; }
}

// Fast, accurate exp(-20*c) for c in [0,1): 2^y split + degree-7 Taylor.
// |rel err| ~ 1e-8 truncation + ~2 ulp rounding. No MUFU.
__device__ __forceinline__ float kexp(float c) {
    float y  = c * -28.853900817779268f;        // -20 * log2(e) * c
    int   ri = __float2int_rn(y);
    float f  = y - (float)ri;                   // f in [-0.5, 0.5]
    float x  = f * 0.69314718055994531f;        // f*ln2, |x| <= 0.3466
    float p  = 1.9841269841e-4f;                // 1/5040
    p = fmaf(p, x, 1.3888888889e-3f);           // 1/720
    p = fmaf(p, x, 8.3333333333e-3f);           // 1/120
    p = fmaf(p, x, 4.1666666667e-2f);           // 1/24
    p = fmaf(p, x, 1.6666666667e-1f);           // 1/6
    p = fmaf(p, x, 0.5f);
    p = fmaf(p, x, 1.0f);
    p = fmaf(p, x, 1.0f);
    return p * __int_as_float((ri + 127) << 23); // ri in [-29,0] -> normal
}

// Sense-reversing grid barrier. All GRID blocks guaranteed co-resident.
__device__ __forceinline__ void gridBarrier(unsigned gen) {
    __syncthreads();
    if (threadIdx.x == 0) {
        __threadfence();                         // release prior writes
        if (atomicAdd(&g_barCount, 1u) == GRID - 1) {
            atomicExch(&g_barCount, 0u);
            __threadfence();
            atomicExch(&g_barGen, gen + 1u);
        } else {
            while (atomicAdd(&g_barGen, 0u) < gen + 1u) { __nanosleep(64); }
        }
        __threadfence();
    }
    __syncthreads();
}

// ---------------------------------------------------------------------------
// Persistent fused Sinkhorn. Block (b, sl) owns rows [sl*256, sl*256+256) of
// batch b. Per iteration: ONE pass over its 1 MB K slice computes both the
// row update (u) and register-accumulated column partials; one grid barrier;
// each block redundantly finalizes v[b,:] into shared memory.
// ---------------------------------------------------------------------------
__global__ void __launch_bounds__(TPB) sinkhornKernel(
    const float* __restrict__ cost, const float* __restrict__ src,
    const float* __restrict__ tgt, float* __restrict__ out) {

    __shared__ float sv[M];          // v for this batch
    __shared__ float su[2][16];      // double-buffered u of current row group
    __shared__ float schg[16];       // per-warp change max

    const int t    = threadIdx.x;
    const int w    = t >> 5;
    const int lane = t & 31;
    const int b    = blockIdx.x >> 2;
    const int sl   = blockIdx.x & 3;
    const int rowBase = (b << 10) + (sl << 8);
    const size_t elemBase = (size_t)rowBase << 10;

    // ---- prologue: convert own K slice (1 MB), init v = 1 ----
    {
        const float4* Cr = (const float4*)(cost + elemBase);
        float4*       Kw = (float4*)(g_K + elemBase);
        for (int i = t; i < 256 * 256; i += TPB) {
            float4 c = Cr[i];
            float4 k;
            k.x = kexp(c.x); k.y = kexp(c.y); k.z = kexp(c.z); k.w = kexp(c.w);
            Kw[i] = k;
        }
    }
    for (int i = t; i < M; i += TPB) sv[i] = 1.0f;
    __syncthreads();

    const float4* sv4 = (const float4*)sv;
    unsigned gen = 0;

    for (int iter = 0; iter < MAX_ITER; ++iter) {
        float2 acc   = make_float2(0.f, 0.f);  // this thread's 2 column sums
        float  chmax = 0.f;                    // lane0-only running max
        float4 kreg[8];

        // --- group 0: step A (row dot -> u_new) ---
        {
            int row = rowBase + w;
            const float4* Kr = (const float4*)(g_K + ((size_t)row << 10));
            #pragma unroll
            for (int i = 0; i < 8; ++i) kreg[i] = Kr[i * 32 + lane];
            float s = 0.f;
            #pragma unroll
            for (int i = 0; i < 8; ++i) {
                float4 vv = sv4[i * 32 + lane];
                s += kreg[i].x * vv.x + kreg[i].y * vv.y
                   + kreg[i].z * vv.z + kreg[i].w * vv.w;
            }
            #pragma unroll
            for (int o = 16; o; o >>= 1) s += __shfl_xor_sync(0xFFFFFFFFu, s, o);
            if (lane == 0) {
                float old = (iter == 0) ? 1.0f : g_u[row];
                float nu  = (__ldg(src + row) + 1e-12f) / s;
                g_u[row]  = nu;
                chmax = fmaxf(chmax, fabsf(logf(nu / old)));
                su[0][w] = nu;
            }
        }
        __syncthreads();

        // --- pipelined groups: issue loads(g), colAcc(g-1) from L1, dot(g) ---
        for (int g = 1; g < 16; ++g) {
            int row = rowBase + (g << 4) + w;
            const float4* Kr = (const float4*)(g_K + ((size_t)row << 10));
            #pragma unroll
            for (int i = 0; i < 8; ++i) kreg[i] = Kr[i * 32 + lane];

            // step B for group g-1: re-read from L1, FMA into register acc
            {
                const float* Kg = g_K
                    + (((size_t)(rowBase + ((g - 1) << 4))) << 10) + 2 * t;
                #pragma unroll
                for (int r = 0; r < 16; ++r) {
                    float uu = su[(g - 1) & 1][r];
                    float2 k2 = *(const float2*)(Kg + ((size_t)r << 10));
                    acc.x = fmaf(k2.x, uu, acc.x);
                    acc.y = fmaf(k2.y, uu, acc.y);
                }
            }

            float s = 0.f;
            #pragma unroll
            for (int i = 0; i < 8; ++i) {
                float4 vv = sv4[i * 32 + lane];
                s += kreg[i].x * vv.x + kreg[i].y * vv.y
                   + kreg[i].z * vv.z + kreg[i].w * vv.w;
            }
            #pragma unroll
            for (int o = 16; o; o >>= 1) s += __shfl_xor_sync(0xFFFFFFFFu, s, o);
            if (lane == 0) {
                float old = (iter == 0) ? 1.0f : g_u[row];
                float nu  = (__ldg(src + row) + 1e-12f) / s;
                g_u[row]  = nu;
                chmax = fmaxf(chmax, fabsf(logf(nu / old)));
                su[g & 1][w] = nu;
            }
            __syncthreads();
        }

        // --- final step B (group 15) ---
        {
            const float* Kg = g_K + (((size_t)(rowBase + (15 << 4))) << 10) + 2 * t;
            #pragma unroll
            for (int r = 0; r < 16; ++r) {
                float uu = su[1][r];
                float2 k2 = *(const float2*)(Kg + ((size_t)r << 10));
                acc.x = fmaf(k2.x, uu, acc.x);
                acc.y = fmaf(k2.y, uu, acc.y);
            }
        }

        // change reduction: one global atomic per block
        if (lane == 0) schg[w] = chmax;
        __syncthreads();
        if (t == 0) {
            float m = schg[0];
            #pragma unroll
            for (int i = 1; i < 16; ++i) m = fmaxf(m, schg[i]);
            atomicMax(&g_change[iter], __float_as_int(m));
        }

        // write this block's column partials (parity-buffered)
        {
            float2* pp = (float2*)(g_partial
                + ((size_t)(iter & 1) * B * 4 + (size_t)b * 4 + sl) * M);
            pp[t] = acc;
        }

        gridBarrier(gen); ++gen;

        // --- v-phase: every block of batch b redundantly builds full v ---
        {
            const float* pb = g_partial
                + ((size_t)(iter & 1) * B * 4 + (size_t)b * 4) * M;
            for (int c = t; c < M; c += TPB) {
                float ssum = __ldcg(pb + c) + __ldcg(pb + M + c)
                           + __ldcg(pb + 2 * M + c) + __ldcg(pb + 3 * M + c);
                sv[c] = (__ldg(tgt + (b << 10) + c) + 1e-12f) / ssum;
            }
        }
        float ch = __int_as_float(__ldcg((const int*)&g_change[iter]));
        __syncthreads();           // sv complete before epilogue / next iter
        if (ch < TOL) break;       // uniform across grid (same global value)
    }

    // ---- epilogue: T = u * K * v for own rows ----
    for (int g = 0; g < 16; ++g) {
        int row = rowBase + (g << 4) + w;
        float u = g_u[row];
        const float4* Kr = (const float4*)(g_K + ((size_t)row << 10));
        float4*       Or = (float4*)(out + ((size_t)row << 10));
        #pragma unroll
        for (int i = 0; i < 8; ++i) {
            int idx = i * 32 + lane;
            float4 k = Kr[idx];
            float4 vv = sv4[idx];
            float4 o;
            o.x = u * k.x * vv.x;
            o.y = u * k.y * vv.y;
            o.z = u * k.z * vv.z;
            o.w = u * k.w * vv.w;
            Or[idx] = o;
        }
    }
}

// ---------------------------------------------------------------------------
extern "C" void kernel_launch(void* const* d_in, const int* in_sizes, int n_in,
                              void* d_out, int out_size) {
    const float* cost = (const float*)d_in[0];  // [B,N,M]
    const float* src  = (const float*)d_in[1];  // [B,N]
    const float* tgt  = (const float*)d_in[2];  // [B,M]
    float* out = (float*)d_out;                 // [B,N,M]

    initKernel<<<1, 64>>>();
    sinkhornKernel<<<GRID, TPB>>>(cost, src, tgt, out);
}

// round 5
// speedup vs baseline: 4.3464x; 2.0199x over previous
#include <cuda_runtime.h>
#include <cuda_fp16.h>
#include <cstdint>

#define B 32
#define N 1024
#define M 1024
#define TOL 0.001f
#define MAX_ITER 50
#define GRID 256          // 8 blocks per batch; <= 2*SMs => co-resident w/ launch_bounds(512,2)
#define TPB 512
#define RPB 128           // rows per block
#define EM105 2.7536449349747158e-5f   // exp(-10.5): scaled-u init (log_u0 = 0)

// ---------------------------------------------------------------------------
// Device scratch (static; no allocation anywhere)
// ---------------------------------------------------------------------------
__device__ __half   g_K16[(size_t)B * N * M];    // 64 MB: e^10.5 * exp(-20c), L2-resident
__device__ float    g_partial[2 * GRID * M];     // double-buffered col partials
__device__ int      g_change[MAX_ITER];          // per-iter max |dlog u| (float bits)
__device__ unsigned g_barCount;
__device__ unsigned g_barGen;

__global__ void initKernel() {
    int i = threadIdx.x;
    if (i < MAX_ITER) g_change[i] = 0;
    if (i == 0) { g_barCount = 0u; g_barGen = 0u; }
}

// exp(10.5 - 20c) for c in [0,1): 2^ri * poly(f*ln2). FMA-only, ~1e-8 rel err.
__device__ __forceinline__ float kexp10(float c) {
    float y  = fmaf(c, -28.853900817779268f, 15.148297929334116f); // (10.5-20c)*log2e
    int   ri = __float2int_rn(y);
    float x  = (y - (float)ri) * 0.69314718055994531f;             // |x| <= 0.347
    float p  = 1.9841269841e-4f;
    p = fmaf(p, x, 1.3888888889e-3f);
    p = fmaf(p, x, 8.3333333333e-3f);
    p = fmaf(p, x, 4.1666666667e-2f);
    p = fmaf(p, x, 1.6666666667e-1f);
    p = fmaf(p, x, 0.5f);
    p = fmaf(p, x, 1.0f);
    p = fmaf(p, x, 1.0f);
    return p * __int_as_float((ri + 127) << 23);                   // ri in [-14,16]
}

__device__ __forceinline__ float dot8(uint4 kq, float4 va, float4 vb) {
    float2 f0 = __half22float2(*(__half2*)&kq.x);
    float2 f1 = __half22float2(*(__half2*)&kq.y);
    float2 f2 = __half22float2(*(__half2*)&kq.z);
    float2 f3 = __half22float2(*(__half2*)&kq.w);
    return f0.x*va.x + f0.y*va.y + f1.x*va.z + f1.y*va.w
         + f2.x*vb.x + f2.y*vb.y + f3.x*vb.z + f3.y*vb.w;
}

__device__ __forceinline__ void gridBarrier(unsigned gen) {
    __syncthreads();
    if (threadIdx.x == 0) {
        __threadfence();
        if (atomicAdd(&g_barCount, 1u) == GRID - 1) {
            atomicExch(&g_barCount, 0u);
            __threadfence();
            atomicExch(&g_barGen, gen + 1u);
        } else {
            while (atomicAdd(&g_barGen, 0u) < gen + 1u) { __nanosleep(64); }
        }
        __threadfence();
    }
    __syncthreads();
}

// ---------------------------------------------------------------------------
// Persistent fused Sinkhorn. Block (b, sl) owns 128 rows of batch b.
// Per iter: row dots (K16 from L2) -> u in smem; col partials re-read K16 from
// L1 with uint4 loads into 8 register accumulators; one grid barrier; each
// block redundantly finalizes v[b,:].
// ---------------------------------------------------------------------------
__global__ void __launch_bounds__(TPB, 2) sinkhornKernel(
    const float* __restrict__ cost, const float* __restrict__ src,
    const float* __restrict__ tgt, float* __restrict__ out) {

    __shared__ float sv[M];          // v for this batch (fp32)
    __shared__ float suAll[RPB];     // scaled u' for this block's rows
    __shared__ float sacc[4][M];     // col-partial staging (4 row-subsets)
    __shared__ float schg[16];

    const int t    = threadIdx.x;
    const int w    = t >> 5;
    const int lane = t & 31;
    const int b    = blockIdx.x >> 3;
    const int rowBase = (b << 10) + ((blockIdx.x & 7) << 7);
    const size_t elemBase = (size_t)rowBase << 10;

    const float4* Cr  = (const float4*)(cost + elemBase);
    const float4* sv4 = (const float4*)sv;

    // ---- prologue: convert own 128-row slice to scaled fp16 ----
    {
        uint4* Kw = (uint4*)(g_K16 + elemBase);
        #pragma unroll 4
        for (int i = t; i < RPB * M / 8; i += TPB) {
            float4 c0 = Cr[2 * i], c1 = Cr[2 * i + 1];
            __half2 h0 = __floats2half2_rn(kexp10(c0.x), kexp10(c0.y));
            __half2 h1 = __floats2half2_rn(kexp10(c0.z), kexp10(c0.w));
            __half2 h2 = __floats2half2_rn(kexp10(c1.x), kexp10(c1.y));
            __half2 h3 = __floats2half2_rn(kexp10(c1.z), kexp10(c1.w));
            uint4 pk;
            pk.x = *(unsigned*)&h0; pk.y = *(unsigned*)&h1;
            pk.z = *(unsigned*)&h2; pk.w = *(unsigned*)&h3;
            Kw[i] = pk;
        }
    }
    for (int i = t; i < M; i += TPB) sv[i] = 1.0f;
    if (t < RPB) suAll[t] = EM105;   // exp(log_u0=0) * e^-10.5
    __syncthreads();

    unsigned gen = 0;
    int iter = 0;
    for (; iter < MAX_ITER; ++iter) {
        float acc[8];
        #pragma unroll
        for (int j = 0; j < 8; ++j) acc[j] = 0.f;
        float chmax = 0.f;

        const int cg = t & 127, rs = t >> 7;

        #pragma unroll
        for (int g = 0; g < 2; ++g) {
            // --- row dots: warp w handles 4 rows, sharing each sv read ---
            {
                int r0 = (g << 6) + (w << 2);
                const uint4* K0 = (const uint4*)g_K16 + (((size_t)(rowBase + r0)) << 7);
                float s0 = 0.f, s1 = 0.f, s2 = 0.f, s3 = 0.f;
                #pragma unroll
                for (int i = 0; i < 4; ++i) {
                    int ci = i * 32 + lane;
                    uint4 ka = K0[ci];
                    uint4 kb = K0[128 + ci];
                    uint4 kc = K0[256 + ci];
                    uint4 kd = K0[384 + ci];
                    float4 va = sv4[2 * ci], vb = sv4[2 * ci + 1];
                    s0 += dot8(ka, va, vb);
                    s1 += dot8(kb, va, vb);
                    s2 += dot8(kc, va, vb);
                    s3 += dot8(kd, va, vb);
                }
                #pragma unroll
                for (int o = 16; o; o >>= 1) {
                    s0 += __shfl_xor_sync(0xFFFFFFFFu, s0, o);
                    s1 += __shfl_xor_sync(0xFFFFFFFFu, s1, o);
                    s2 += __shfl_xor_sync(0xFFFFFFFFu, s2, o);
                    s3 += __shfl_xor_sync(0xFFFFFFFFu, s3, o);
                }
                if (lane == 0) {
                    float ss[4] = {s0, s1, s2, s3};
                    #pragma unroll
                    for (int j = 0; j < 4; ++j) {
                        float old = suAll[r0 + j];
                        float nu  = (__ldg(src + rowBase + r0 + j) + 1e-12f) / ss[j];
                        suAll[r0 + j] = nu;
                        chmax = fmaxf(chmax, fabsf(logf(nu / old)));
                    }
                }
            }
            __syncthreads();

            // --- col acc: thread (cg,rs): cols cg*8..+7 over 16 rows (L1 hits) ---
            {
                int r0 = (g << 6) + (rs << 4);
                const uint4* Kc = (const uint4*)g_K16
                    + (((size_t)(rowBase + r0)) << 7) + cg;
                #pragma unroll
                for (int j = 0; j < 16; ++j) {
                    uint4 kq = Kc[(size_t)j << 7];
                    float uu = suAll[r0 + j];
                    float2 f0 = __half22float2(*(__half2*)&kq.x);
                    float2 f1 = __half22float2(*(__half2*)&kq.y);
                    float2 f2 = __half22float2(*(__half2*)&kq.z);
                    float2 f3 = __half22float2(*(__half2*)&kq.w);
                    acc[0] = fmaf(f0.x, uu, acc[0]);
                    acc[1] = fmaf(f0.y, uu, acc[1]);
                    acc[2] = fmaf(f1.x, uu, acc[2]);
                    acc[3] = fmaf(f1.y, uu, acc[3]);
                    acc[4] = fmaf(f2.x, uu, acc[4]);
                    acc[5] = fmaf(f2.y, uu, acc[5]);
                    acc[6] = fmaf(f3.x, uu, acc[6]);
                    acc[7] = fmaf(f3.y, uu, acc[7]);
                }
            }
        }

        // --- stage partials, reduce 4 row-subsets, write block partial ---
        #pragma unroll
        for (int j = 0; j < 8; ++j) sacc[rs][cg * 8 + j] = acc[j];
        if (lane == 0) schg[w] = chmax;
        __syncthreads();
        {
            float* pp = g_partial + ((size_t)(iter & 1) * GRID + blockIdx.x) * M;
            for (int c = t; c < M; c += TPB)
                pp[c] = (sacc[0][c] + sacc[1][c]) + (sacc[2][c] + sacc[3][c]);
        }
        if (t == 0) {
            float m = schg[0];
            #pragma unroll
            for (int i = 1; i < 16; ++i) m = fmaxf(m, schg[i]);
            atomicMax(&g_change[iter], __float_as_int(m));
        }

        gridBarrier(gen); ++gen;

        // --- v-phase: every block of batch b builds full v ---
        {
            const float* pb = g_partial + ((size_t)(iter & 1) * GRID + (b << 3)) * M;
            for (int c = t; c < M; c += TPB) {
                float ssum = 0.f;
                #pragma unroll
                for (int k = 0; k < 8; ++k) ssum += __ldcg(pb + k * M + c);
                sv[c] = (__ldg(tgt + (b << 10) + c) + 1e-12f) / ssum;
            }
        }
        float ch = __int_as_float(__ldcg((const int*)&g_change[iter]));
        __syncthreads();            // sv complete before next iter / epilogue
        if (ch < TOL) break;        // uniform across grid
    }

    // ---- epilogue: T = u' * exp(10.5-20c) * v  (exact fp32 K from cost) ----
    {
        float4* Ow = (float4*)(out + elemBase);
        #pragma unroll 2
        for (int i = t; i < RPB * 256; i += TPB) {
            float u = suAll[i >> 8];
            float4 c  = Cr[i];
            float4 vv = sv4[i & 255];
            float4 o;
            o.x = u * kexp10(c.x) * vv.x;
            o.y = u * kexp10(c.y) * vv.y;
            o.z = u * kexp10(c.z) * vv.z;
            o.w = u * kexp10(c.w) * vv.w;
            Ow[i] = o;
        }
    }
}

// ---------------------------------------------------------------------------
extern "C" void kernel_launch(void* const* d_in, const int* in_sizes, int n_in,
                              void* d_out, int out_size) {
    const float* cost = (const float*)d_in[0];
    const float* src  = (const float*)d_in[1];
    const float* tgt  = (const float*)d_in[2];
    float* out = (float*)d_out;

    initKernel<<<1, 64>>>();
    sinkhornKernel<<<GRID, TPB>>>(cost, src, tgt, out);
}

// round 6
// speedup vs baseline: 4.5921x; 1.0565x over previous
#include <cuda_runtime.h>
#include <cuda_fp16.h>
#include <cstdint>

#define B 32
#define N 1024
#define M 1024
#define TOL 0.001f
#define MAX_ITER 50
#define GRID 256          // 8 blocks/batch; 2 blocks/SM co-resident (barrier-safe)
#define TPB 512
#define RPB 128           // rows per block
#define EM105 2.7536449349747158e-5f   // exp(-10.5): scaled-u init (log_u0 = 0)

// ---------------------------------------------------------------------------
__device__ __half   g_K16[(size_t)B * N * M];    // 64 MB: e^10.5 * exp(-20c), L2-resident
__device__ float    g_partial[2 * GRID * M];     // double-buffered col partials
__device__ int      g_change[MAX_ITER];          // per-iter max |dlog u| (float bits)
__device__ unsigned g_barCount;
__device__ unsigned g_barGen;

__global__ void initKernel() {
    int i = threadIdx.x;
    if (i < MAX_ITER) g_change[i] = 0;
    if (i == 0) { g_barCount = 0u; g_barGen = 0u; }
}

// exp(10.5 - 20c), c in [0,1): 2^ri * poly(f*ln2). FMA-only, ~1e-8 rel err.
__device__ __forceinline__ float kexp10(float c) {
    float y  = fmaf(c, -28.853900817779268f, 15.148297929334116f);
    int   ri = __float2int_rn(y);
    float x  = (y - (float)ri) * 0.69314718055994531f;             // |x| <= 0.347
    float p  = 1.9841269841e-4f;
    p = fmaf(p, x, 1.3888888889e-3f);
    p = fmaf(p, x, 8.3333333333e-3f);
    p = fmaf(p, x, 4.1666666667e-2f);
    p = fmaf(p, x, 1.6666666667e-1f);
    p = fmaf(p, x, 0.5f);
    p = fmaf(p, x, 1.0f);
    p = fmaf(p, x, 1.0f);
    return p * __int_as_float((ri + 127) << 23);                   // ri in [-14,16]
}

__device__ __forceinline__ float dot8(uint4 kq, float4 va, float4 vb) {
    float2 f0 = __half22float2(*(__half2*)&kq.x);
    float2 f1 = __half22float2(*(__half2*)&kq.y);
    float2 f2 = __half22float2(*(__half2*)&kq.z);
    float2 f3 = __half22float2(*(__half2*)&kq.w);
    return f0.x*va.x + f0.y*va.y + f1.x*va.z + f1.y*va.w
         + f2.x*vb.x + f2.y*vb.y + f3.x*vb.z + f3.y*vb.w;
}

__device__ __forceinline__ void gridBarrier(unsigned gen) {
    __syncthreads();
    if (threadIdx.x == 0) {
        __threadfence();
        if (atomicAdd(&g_barCount, 1u) == GRID - 1) {
            atomicExch(&g_barCount, 0u);
            __threadfence();
            atomicExch(&g_barGen, gen + 1u);
        } else {
            while (atomicAdd(&g_barGen, 0u) < gen + 1u) { __nanosleep(64); }
        }
        __threadfence();
    }
    __syncthreads();
}

// ---------------------------------------------------------------------------
// Persistent fused Sinkhorn.
//  prologue: convert cost->K16 AND accumulate row sums (v0 = 1) -> u1
//  loop it:  [it>0: row dots for u_{it+1}] fused per 32-row group with col acc
//            -> partials -> grid barrier -> v_{it+1} -> break on change < TOL
//  epilogue: T = u' * K16 * v  (streaming stores)
// ---------------------------------------------------------------------------
__global__ void __launch_bounds__(TPB, 2) sinkhornKernel(
    const float* __restrict__ cost, const float* __restrict__ src,
    const float* __restrict__ tgt, float* __restrict__ out) {

    __shared__ float sv[M];          // v for this batch
    __shared__ float suAll[RPB];     // scaled u' for this block's rows
    __shared__ float sacc[4][M];     // col-partial staging (4 row-subsets)
    __shared__ float schg[16];
    __shared__ float srow[RPB];      // prologue row sums
    __shared__ int   schgBits;

    const int t    = threadIdx.x;
    const int w    = t >> 5;
    const int lane = t & 31;
    const int b    = blockIdx.x >> 3;
    const int rowBase = (b << 10) + ((blockIdx.x & 7) << 7);
    const size_t elemBase = (size_t)rowBase << 10;

    const float4* Cr  = (const float4*)(cost + elemBase);
    const float4* sv4 = (const float4*)sv;

    for (int i = t; i < M; i += TPB) sv[i] = 1.0f;
    if (t < RPB) srow[t] = 0.0f;
    if (t == 0)  schgBits = 0;
    __syncthreads();

    // ---- prologue: convert 128-row slice to scaled fp16 + row sums (v=1) ----
    {
        uint4* Kw = (uint4*)(g_K16 + elemBase);
        #pragma unroll 2
        for (int k = 0; k < 32; ++k) {
            int i = k * TPB + t;                       // uint4 index in tile
            float4 c0 = Cr[2 * i], c1 = Cr[2 * i + 1];
            float f0 = kexp10(c0.x), f1 = kexp10(c0.y);
            float f2 = kexp10(c0.z), f3 = kexp10(c0.w);
            float f4 = kexp10(c1.x), f5 = kexp10(c1.y);
            float f6 = kexp10(c1.z), f7 = kexp10(c1.w);
            __half2 h0 = __floats2half2_rn(f0, f1), h1 = __floats2half2_rn(f2, f3);
            __half2 h2 = __floats2half2_rn(f4, f5), h3 = __floats2half2_rn(f6, f7);
            uint4 pk;
            pk.x = *(unsigned*)&h0; pk.y = *(unsigned*)&h1;
            pk.z = *(unsigned*)&h2; pk.w = *(unsigned*)&h3;
            Kw[i] = pk;
            float s = ((f0 + f1) + (f2 + f3)) + ((f4 + f5) + (f6 + f7));
            #pragma unroll
            for (int o = 16; o; o >>= 1) s += __shfl_xor_sync(0xFFFFFFFFu, s, o);
            if (lane == 0) atomicAdd(&srow[i >> 7], s);   // i>>7 uniform in warp
        }
    }
    __syncthreads();
    if (t < RPB) {                    // u1 = (src+eps)/rowsum ; change_1
        float nu = (__ldg(src + rowBase + t) + 1e-12f) / srow[t];
        suAll[t] = nu;
        atomicMax(&schgBits, __float_as_int(fabsf(logf(nu / EM105))));
    }
    __syncthreads();
    if (t == 0) atomicMax(&g_change[0], schgBits);

    unsigned gen = 0;
    const int cg = t & 127, rs = t >> 7;

    for (int it = 0; it < MAX_ITER; ++it) {
        float acc[8];
        #pragma unroll
        for (int j = 0; j < 8; ++j) acc[j] = 0.f;
        float chmax = 0.f;

        #pragma unroll
        for (int g = 0; g < 4; ++g) {                    // 32-row groups
            if (it > 0) {
                // --- row dots: warp w handles rows r0, r0+1 ---
                int r0 = (g << 5) + (w << 1);
                const uint4* K0 = (const uint4*)g_K16 + (((size_t)(rowBase + r0)) << 7);
                float s0 = 0.f, s1 = 0.f;
                #pragma unroll
                for (int i = 0; i < 4; ++i) {
                    int ci = i * 32 + lane;
                    uint4 ka = K0[ci];
                    uint4 kb = K0[128 + ci];
                    float4 va = sv4[2 * ci], vb = sv4[2 * ci + 1];
                    s0 += dot8(ka, va, vb);
                    s1 += dot8(kb, va, vb);
                }
                #pragma unroll
                for (int o = 16; o; o >>= 1) {
                    s0 += __shfl_xor_sync(0xFFFFFFFFu, s0, o);
                    s1 += __shfl_xor_sync(0xFFFFFFFFu, s1, o);
                }
                if (lane == 0) {
                    float o0 = suAll[r0], o1 = suAll[r0 + 1];
                    float n0 = (__ldg(src + rowBase + r0)     + 1e-12f) / s0;
                    float n1 = (__ldg(src + rowBase + r0 + 1) + 1e-12f) / s1;
                    suAll[r0] = n0; suAll[r0 + 1] = n1;
                    chmax = fmaxf(chmax,
                            fmaxf(fabsf(logf(n0 / o0)), fabsf(logf(n1 / o1))));
                }
                __syncthreads();
            }
            // --- col acc: thread (cg,rs): cols cg*8..+7 over 8 rows (L1-hot) ---
            {
                int r0 = (g << 5) + (rs << 3);
                const uint4* Kc = (const uint4*)g_K16
                    + (((size_t)(rowBase + r0)) << 7) + cg;
                #pragma unroll
                for (int j = 0; j < 8; ++j) {
                    uint4 kq = Kc[(size_t)j << 7];
                    float uu = suAll[r0 + j];
                    float2 f0 = __half22float2(*(__half2*)&kq.x);
                    float2 f1 = __half22float2(*(__half2*)&kq.y);
                    float2 f2 = __half22float2(*(__half2*)&kq.z);
                    float2 f3 = __half22float2(*(__half2*)&kq.w);
                    acc[0] = fmaf(f0.x, uu, acc[0]);
                    acc[1] = fmaf(f0.y, uu, acc[1]);
                    acc[2] = fmaf(f1.x, uu, acc[2]);
                    acc[3] = fmaf(f1.y, uu, acc[3]);
                    acc[4] = fmaf(f2.x, uu, acc[4]);
                    acc[5] = fmaf(f2.y, uu, acc[5]);
                    acc[6] = fmaf(f3.x, uu, acc[6]);
                    acc[7] = fmaf(f3.y, uu, acc[7]);
                }
            }
        }

        // --- stage partials, reduce 4 row-subsets, write block partial ---
        #pragma unroll
        for (int j = 0; j < 8; ++j) sacc[rs][cg * 8 + j] = acc[j];
        if (lane == 0) schg[w] = chmax;
        __syncthreads();
        {
            float* pp = g_partial + ((size_t)(it & 1) * GRID + blockIdx.x) * M;
            for (int c = t; c < M; c += TPB)
                pp[c] = (sacc[0][c] + sacc[1][c]) + (sacc[2][c] + sacc[3][c]);
        }
        if (t == 0 && it > 0) {
            float m = schg[0];
            #pragma unroll
            for (int i = 1; i < 16; ++i) m = fmaxf(m, schg[i]);
            atomicMax(&g_change[it], __float_as_int(m));
        }

        gridBarrier(gen); ++gen;

        // --- v-phase: every block of batch b builds full v ---
        {
            const float* pb = g_partial + ((size_t)(it & 1) * GRID + (b << 3)) * M;
            for (int c = t; c < M; c += TPB) {
                float ssum = 0.f;
                #pragma unroll
                for (int k = 0; k < 8; ++k) ssum += __ldcg(pb + k * M + c);
                sv[c] = (__ldg(tgt + (b << 10) + c) + 1e-12f) / ssum;
            }
        }
        float ch = __int_as_float(__ldcg((const int*)&g_change[it]));
        __syncthreads();            // sv complete before next iter / epilogue
        if (ch < TOL) break;        // uniform across grid
    }

    // ---- epilogue: T = u' * K16 * v  (K16 from L2, streaming out stores) ----
    {
        const uint4* Kr = (const uint4*)(g_K16 + elemBase);
        float4* Ow = (float4*)(out + elemBase);
        #pragma unroll 2
        for (int k = 0; k < 32; ++k) {
            int i = k * TPB + t;
            uint4 kq = Kr[i];
            float u = suAll[i >> 7];
            float4 va = sv4[(i & 127) * 2], vb = sv4[(i & 127) * 2 + 1];
            float2 f0 = __half22float2(*(__half2*)&kq.x);
            float2 f1 = __half22float2(*(__half2*)&kq.y);
            float2 f2 = __half22float2(*(__half2*)&kq.z);
            float2 f3 = __half22float2(*(__half2*)&kq.w);
            float4 o0, o1;
            o0.x = u * f0.x * va.x;
            o0.y = u * f0.y * va.y;
            o0.z = u * f1.x * va.z;
            o0.w = u * f1.y * va.w;
            o1.x = u * f2.x * vb.x;
            o1.y = u * f2.y * vb.y;
            o1.z = u * f3.x * vb.z;
            o1.w = u * f3.y * vb.w;
            __stcs(Ow + 2 * i,     o0);
            __stcs(Ow + 2 * i + 1, o1);
        }
    }
}

// ---------------------------------------------------------------------------
extern "C" void kernel_launch(void* const* d_in, const int* in_sizes, int n_in,
                              void* d_out, int out_size) {
    const float* cost = (const float*)d_in[0];
    const float* src  = (const float*)d_in[1];
    const float* tgt  = (const float*)d_in[2];
    float* out = (float*)d_out;

    initKernel<<<1, 64>>>();
    sinkhornKernel<<<GRID, TPB>>>(cost, src, tgt, out);
}